// round 7
// baseline (speedup 1.0000x reference)
#include <cuda_runtime.h>
#include <cstdint>

// EmbeddingWithDropout:
//   out[t, :] = weight[x[t], :] * ((u[x[t]] >= 0.1f) ? (1.0f/0.9f) : 0.0f)
// x: int32 [131072], weight: f32 [100000,128], u: f32 [100000], out: f32 [131072,128]
//
// Round-6: ptxas only permits L2::evict_* on 256-bit accesses, so the kernel is
// rebuilt around v8.b32 loads/stores:
//   - warp covers 8 tokens in 4 waves; per wave, lanes 0-15 serve token (base+2w),
//     lanes 16-31 serve token (base+2w+1); each lane moves one 32 B segment.
//   - weight gathers: ld.global.nc.L2::evict_last.v8.b32  (pin 51 MB table in L2)
//   - output stores:  st.global.L2::evict_first.v8.b32    (write stream = victim)
// Halves LDG/STG instruction count vs float4 as a side benefit.

#define WAVES 4  // tokens per warp = 2 * WAVES = 8

__device__ __forceinline__ void ldg_el_v8(const float* p, uint32_t* v) {
    asm("ld.global.nc.L2::evict_last.v8.b32 {%0,%1,%2,%3,%4,%5,%6,%7}, [%8];"
        : "=r"(v[0]), "=r"(v[1]), "=r"(v[2]), "=r"(v[3]),
          "=r"(v[4]), "=r"(v[5]), "=r"(v[6]), "=r"(v[7])
        : "l"(p));
}

__device__ __forceinline__ void stg_ef_v8(float* p, const uint32_t* v) {
    asm volatile("st.global.L2::evict_first.v8.b32 [%0], {%1,%2,%3,%4,%5,%6,%7,%8};"
                 :: "l"(p),
                    "r"(v[0]), "r"(v[1]), "r"(v[2]), "r"(v[3]),
                    "r"(v[4]), "r"(v[5]), "r"(v[6]), "r"(v[7])
                 : "memory");
}

__global__ void __launch_bounds__(256, 4)
embedding_dropout_kernel(const int* __restrict__ x,
                         const float* __restrict__ weight,   // [vocab,128]
                         const float* __restrict__ u,        // [vocab]
                         float* __restrict__ out,            // [n_tok,128]
                         int n_tok)
{
    const int gtid  = blockIdx.x * blockDim.x + threadIdx.x;
    const int warp  = gtid >> 5;
    const int lane  = threadIdx.x & 31;
    const int tpair = lane >> 4;     // which of the 2 tokens in this wave
    const int seg   = lane & 15;     // 32-byte segment within the 512 B row
    const int base  = warp * (2 * WAVES);
    if (base >= n_tok) return;

    if (base + 2 * WAVES <= n_tok) {
        // ---- Wave 1: 8 index loads (2 distinct addresses per warp-wave) ----
        int rows[WAVES];
        #pragma unroll
        for (int w = 0; w < WAVES; w++)
            rows[w] = __ldg(&x[base + 2 * w + tpair]);

        // ---- Wave 2: u-loads + 256-bit row gathers, all independent ----
        float uv[WAVES];
        uint32_t v[WAVES][8];
        #pragma unroll
        for (int w = 0; w < WAVES; w++) {
            uv[w] = __ldg(&u[rows[w]]);
            ldg_el_v8(weight + (size_t)rows[w] * 128 + seg * 8, v[w]);
        }

        // ---- Scale + evict-first 256-bit store ----
        #pragma unroll
        for (int w = 0; w < WAVES; w++) {
            const float keep = (uv[w] >= 0.1f) ? (1.0f / 0.9f) : 0.0f;
            #pragma unroll
            for (int j = 0; j < 8; j++)
                v[w][j] = __float_as_uint(__uint_as_float(v[w][j]) * keep);
            stg_ef_v8(out + (size_t)(base + 2 * w + tpair) * 128 + seg * 8, v[w]);
        }
    } else {
        // ---- Tail path (plain ops, per-token guard) ----
        #pragma unroll
        for (int w = 0; w < WAVES; w++) {
            const int tok = base + 2 * w + tpair;
            if (tok < n_tok) {
                const int row = __ldg(&x[tok]);
                const float keep = (__ldg(&u[row]) >= 0.1f) ? (1.0f / 0.9f) : 0.0f;
                const float4* wp = (const float4*)(weight + (size_t)row * 128 + seg * 8);
                float4 a = __ldg(wp);
                float4 b = __ldg(wp + 1);
                a.x *= keep; a.y *= keep; a.z *= keep; a.w *= keep;
                b.x *= keep; b.y *= keep; b.z *= keep; b.w *= keep;
                float4* op = (float4*)(out + (size_t)tok * 128 + seg * 8);
                op[0] = a;
                op[1] = b;
            }
        }
    }
}

extern "C" void kernel_launch(void* const* d_in, const int* in_sizes, int n_in,
                              void* d_out, int out_size)
{
    const int*   x      = (const int*)d_in[0];
    const float* weight = (const float*)d_in[1];
    const float* u      = (const float*)d_in[2];
    float*       out    = (float*)d_out;

    const int n_tok = in_sizes[0];                           // 131072
    const int threads = 256;                                 // 8 warps/block
    const int tok_per_block = (threads / 32) * (2 * WAVES);  // 64
    const int blocks = (n_tok + tok_per_block - 1) / tok_per_block;

    embedding_dropout_kernel<<<blocks, threads>>>(x, weight, u, out, n_tok);
}